// round 13
// baseline (speedup 1.0000x reference)
#include <cuda_runtime.h>
#include <cuda_fp16.h>
#include <cstdint>

// ---------------- problem constants ----------------
#define HEADS  16
#define BDIM   2048
#define DHEAD  64
#define TOTALD 1024
#define FDIM   4096
#define PDIM   512

#define BM 128
#define BN 128
#define BK 32
#define NTHREADS 256

// ---------------- static scratch (no allocations allowed) ----------------
__device__ __half g_x16[(size_t)BDIM * TOTALD];
__device__ __half g_f16[(size_t)FDIM * TOTALD];
__device__ __half g_p16[(size_t)PDIM * TOTALD];
__device__ __half g_Xp[(size_t)HEADS * BDIM * FDIM];   // relu(xf); Xw = Xp^2 derived in p2
__device__ __half g_B1[(size_t)HEADS * PDIM * FDIM];   // th*Pw + al*Pp
__device__ __half g_B2[(size_t)HEADS * PDIM * FDIM];   // be*Pw
__device__ float  g_xpart[(size_t)HEADS * BDIM * 32];
__device__ float  g_ppart[(size_t)HEADS * PDIM * 32];

// ---------------- helpers ----------------
__device__ __forceinline__ uint32_t smem_u32(const void* p) {
    return (uint32_t)__cvta_generic_to_shared(p);
}
__device__ __forceinline__ void cp_async16(uint32_t dst, const void* src) {
    asm volatile("cp.async.cg.shared.global [%0], [%1], 16;\n" :: "r"(dst), "l"(src));
}
__device__ __forceinline__ void cp_commit() { asm volatile("cp.async.commit_group;\n"); }
__device__ __forceinline__ void cp_wait1()  { asm volatile("cp.async.wait_group 1;\n"); }
__device__ __forceinline__ void cp_wait0()  { asm volatile("cp.async.wait_group 0;\n"); }

// 64B rows, 4x16B chunks swizzle (p01)
__device__ __forceinline__ uint32_t swoff(int row, int chunk) {
    return (uint32_t)(row * 64 + ((chunk ^ ((row >> 1) & 3)) << 4));
}
// 128B rows, 8x16B chunks swizzle (p2)
__device__ __forceinline__ uint32_t swz128(int row, int c) {
    return (uint32_t)(row * 128 + ((c ^ (row & 7)) << 4));
}
__device__ __forceinline__ void ldm_x4(uint32_t addr, uint32_t& r0, uint32_t& r1,
                                       uint32_t& r2, uint32_t& r3) {
    asm volatile("ldmatrix.sync.aligned.m8n8.x4.shared.b16 {%0,%1,%2,%3}, [%4];\n"
                 : "=r"(r0), "=r"(r1), "=r"(r2), "=r"(r3) : "r"(addr));
}
__device__ __forceinline__ void mma16816(float* c, const uint32_t* a, const uint32_t* b) {
    asm volatile("mma.sync.aligned.m16n8k16.row.col.f32.f16.f16.f32 "
                 "{%0,%1,%2,%3}, {%4,%5,%6,%7}, {%8,%9}, {%0,%1,%2,%3};\n"
                 : "+f"(c[0]), "+f"(c[1]), "+f"(c[2]), "+f"(c[3])
                 : "r"(a[0]), "r"(a[1]), "r"(a[2]), "r"(a[3]), "r"(b[0]), "r"(b[1]));
}
__device__ __forceinline__ uint32_t h2sq(uint32_t v) {
    __half2 h = *reinterpret_cast<__half2*>(&v);
    h = __hmul2(h, h);
    return *reinterpret_cast<uint32_t*>(&h);
}

// ---------------- fp32 -> fp16 converts ----------------
__global__ void convert_kernel(const float* __restrict__ x,
                               const float* __restrict__ f,
                               const float* __restrict__ p) {
    int i = blockIdx.x * blockDim.x + threadIdx.x;
    if (i < BDIM * TOTALD)  g_x16[i] = __float2half_rn(x[i]);
    if (i < FDIM * TOTALD)  g_f16[i] = __float2half_rn(f[i]);
    if (i < PDIM * TOTALD)  g_p16[i] = __float2half_rn(p[i]);
}

// ---------------- merged phase-0/1 GEMM (K=64), one launch, fused row-sums ----------------
// grid = (32, 20, 16): y<16 -> x-phase (bm=y*128), y>=16 -> p-phase (bm=(y-16)*128)
#define P01_PITCH 272
#define P01_SMEM (BM * P01_PITCH)

__global__ void __launch_bounds__(NTHREADS)
p01_kernel(const float* __restrict__ theta, const float* __restrict__ alpha,
           const float* __restrict__ beta) {
    extern __shared__ __align__(1024) uint8_t smem[];

    const int tid    = threadIdx.x;
    const int lane   = tid & 31;
    const int warp   = tid >> 5;
    const int warp_m = warp & 3;
    const int warp_n = warp >> 2;
    const int h  = blockIdx.z;
    const bool xphase = (blockIdx.y < HEADS);
    const int bm = (xphase ? blockIdx.y : blockIdx.y - HEADS) * BM;
    const int bn = blockIdx.x * BN;

    const __half* A = (xphase ? g_x16 : g_p16) + h * DHEAD;
    const __half* B = g_f16 + h * DHEAD;
    const int total_kt = DHEAD / BK;
    const uint32_t sbase = smem_u32(smem);

    auto load_tile = [&](int s, int g) {
        const int k0 = g * BK;
        int idx = tid;
#pragma unroll
        for (int r = 0; r < 2; r++, idx += NTHREADS) {
            int row = idx >> 2, ch = idx & 3;
            cp_async16(sbase + s * 8192 + swoff(row, ch),
                       A + (size_t)(bm + row) * TOTALD + k0 + ch * 8);
        }
        idx = tid;
#pragma unroll
        for (int r = 0; r < 2; r++, idx += NTHREADS) {
            int row = idx >> 2, ch = idx & 3;
            cp_async16(sbase + 16384 + s * 8192 + swoff(row, ch),
                       B + (size_t)(bn + row) * TOTALD + k0 + ch * 8);
        }
    };

    float acc[2][8][4];
#pragma unroll
    for (int i = 0; i < 2; i++)
#pragma unroll
        for (int j = 0; j < 8; j++)
#pragma unroll
            for (int q = 0; q < 4; q++) acc[i][j][q] = 0.f;

    const int a_row = warp_m * 32 + (lane & 15);
    const int a_ch  = lane >> 4;
    const int b_row = warp_n * 64 + (lane & 7) + ((lane >> 4) << 3);
    const int b_ch  = (lane >> 3) & 1;

    load_tile(0, 0);
    cp_commit();

    for (int g = 0; g < total_kt; g++) {
        if (g + 1 < total_kt) { load_tile((g + 1) & 1, g + 1); cp_commit(); cp_wait1(); }
        else                  { cp_wait0(); }
        __syncthreads();

        const int s = g & 1;
        const uint32_t sA = sbase + s * 8192;
        const uint32_t sB = sbase + 16384 + s * 8192;
#pragma unroll
        for (int ks = 0; ks < 2; ks++) {
            uint32_t a[2][4];
#pragma unroll
            for (int mi = 0; mi < 2; mi++)
                ldm_x4(sA + swoff(a_row + mi * 16, ks * 2 + a_ch),
                       a[mi][0], a[mi][1], a[mi][2], a[mi][3]);
            uint32_t b[4][4];
#pragma unroll
            for (int nj = 0; nj < 4; nj++)
                ldm_x4(sB + swoff(b_row + nj * 16, ks * 2 + b_ch),
                       b[nj][0], b[nj][1], b[nj][2], b[nj][3]);
#pragma unroll
            for (int mi = 0; mi < 2; mi++)
#pragma unroll
                for (int ni = 0; ni < 8; ni++)
                    mma16816(acc[mi][ni], a[mi], &b[ni >> 1][(ni & 1) * 2]);
        }
        __syncthreads();
    }

    // ---- row-sum partials (w = relu(acc)^2) ----
    float th = 0.f, al = 0.f, be = 0.f;
    if (!xphase) { th = theta[h]; al = alpha[h]; be = beta[h]; }

    float rowsum[2][2] = {{0.f, 0.f}, {0.f, 0.f}};
#pragma unroll
    for (int mi = 0; mi < 2; mi++)
#pragma unroll
        for (int ni = 0; ni < 8; ni++)
#pragma unroll
            for (int q = 0; q < 2; q++) {
                const float p0 = fmaxf(acc[mi][ni][q * 2 + 0], 0.f);
                const float p1 = fmaxf(acc[mi][ni][q * 2 + 1], 0.f);
                rowsum[mi][q] += p0 * p0 + p1 * p1;
            }
#pragma unroll
    for (int mi = 0; mi < 2; mi++)
#pragma unroll
        for (int q = 0; q < 2; q++) {
            float s = rowsum[mi][q];
            s += __shfl_xor_sync(0xffffffffu, s, 1);
            s += __shfl_xor_sync(0xffffffffu, s, 2);
            rowsum[mi][q] = s;
        }
    float* red = reinterpret_cast<float*>(smem);
    if (warp_n == 0 && (lane & 3) == 0) {
#pragma unroll
        for (int mi = 0; mi < 2; mi++)
#pragma unroll
            for (int q = 0; q < 2; q++)
                red[warp_m * 32 + mi * 16 + q * 8 + (lane >> 2)] = rowsum[mi][q];
    }
    __syncthreads();
    if (warp_n == 1 && (lane & 3) == 0) {
#pragma unroll
        for (int mi = 0; mi < 2; mi++)
#pragma unroll
            for (int q = 0; q < 2; q++) {
                const int rl = warp_m * 32 + mi * 16 + q * 8 + (lane >> 2);
                const float tot = red[rl] + rowsum[mi][q];
                if (xphase)
                    g_xpart[((size_t)h * BDIM + bm + rl) * 32 + blockIdx.x] = tot;
                else
                    g_ppart[((size_t)h * PDIM + bm + rl) * 32 + blockIdx.x] = tot;
            }
    }

    // ---- staged, coalesced output passes (1 pass x-phase, 2 passes p-phase) ----
    const int st_r = warp_m * 32 + (lane >> 2);
    const int st_c = warp_n * 64 + (lane & 3) * 2;
    const int npass = xphase ? 1 : 2;
    for (int pass = 0; pass < npass; pass++) {
        __syncthreads();
#pragma unroll
        for (int mi = 0; mi < 2; mi++)
#pragma unroll
            for (int ni = 0; ni < 8; ni++)
#pragma unroll
                for (int q = 0; q < 2; q++) {
                    const float p0 = fmaxf(acc[mi][ni][q * 2 + 0], 0.f);
                    const float p1 = fmaxf(acc[mi][ni][q * 2 + 1], 0.f);
                    const float w0 = p0 * p0, w1 = p1 * p1;
                    __half2 v;
                    if (xphase)
                        v = __floats2half2_rn(p0, p1);
                    else
                        v = (pass == 0) ? __floats2half2_rn(th * w0 + al * p0,
                                                            th * w1 + al * p1)
                                        : __floats2half2_rn(be * w0, be * w1);
                    *reinterpret_cast<__half2*>(smem +
                        (st_r + mi * 16 + q * 8) * P01_PITCH + (st_c + ni * 8) * 2) = v;
                }
        __syncthreads();
        __half* dst;
        if (xphase) dst = g_Xp + (size_t)h * BDIM * FDIM;
        else        dst = (pass == 0 ? g_B1 : g_B2) + (size_t)h * PDIM * FDIM;
#pragma unroll
        for (int i = 0; i < 8; i++) {
            const int idx = tid + i * NTHREADS;
            const int r = idx >> 4, c = idx & 15;
            const uint4 v = *reinterpret_cast<const uint4*>(smem + r * P01_PITCH + c * 16);
            *reinterpret_cast<uint4*>(dst + (size_t)(bm + r) * FDIM + bn + c * 8) = v;
        }
    }
}

// ---------------- phase-2: R8 mainloop + de-batched loads (A+B1 head, B2 mid-compute) ----------------
#define P2_THREADS 128
#define P2_BK 64
#define P2_CHUNKS 64
#define P2_STAGE (3 * BM * P2_BK * 2)         // Xp 16KB + B1 16KB + B2 16KB = 48KB
#define P2_SMEM (2 * P2_STAGE)                // 96KB -> 2 CTAs/SM
#define P2_PITCHW 136
#define P2_SUMOFF (BM * P2_PITCHW)

__global__ void __launch_bounds__(P2_THREADS, 2)
p2_kernel(const float* __restrict__ alpha, const float* __restrict__ beta,
          float* __restrict__ out) {
    extern __shared__ __align__(1024) uint8_t smem[];
    const uint32_t sb = smem_u32(smem);
    const int tid    = threadIdx.x;
    const int lane   = tid & 31;
    const int warp   = tid >> 5;
    const int warp_m = warp & 1;
    const int warp_n = warp >> 1;
    const int h  = blockIdx.z;
    const int bm = blockIdx.y * BM;
    const int bn = blockIdx.x * BN;

    const __half* Ap = g_Xp + (size_t)h * BDIM * FDIM;
    const __half* B1 = g_B1 + (size_t)h * PDIM * FDIM;
    const __half* B2 = g_B2 + (size_t)h * PDIM * FDIM;

    const int pr = tid >> 3, pc = tid & 7;

    auto load_AB1 = [&](int s, int g) {
        const int k0 = g * P2_BK;
        const uint32_t sA  = sb + s * P2_STAGE;
        const uint32_t sB1 = sA + 16384;
#pragma unroll
        for (int i = 0; i < 8; i++) {
            const int row = i * 16 + pr;
            cp_async16(sA + swz128(row, pc), Ap + (size_t)(bm + row) * FDIM + k0 + pc * 8);
        }
#pragma unroll
        for (int i = 0; i < 8; i++) {
            const int row = i * 16 + pr;
            cp_async16(sB1 + swz128(row, pc), B1 + (size_t)(bn + row) * FDIM + k0 + pc * 8);
        }
    };
    auto load_B2 = [&](int s, int g) {
        const int k0 = g * P2_BK;
        const uint32_t sB2 = sb + s * P2_STAGE + 32768;
#pragma unroll
        for (int i = 0; i < 8; i++) {
            const int row = i * 16 + pr;
            cp_async16(sB2 + swz128(row, pc), B2 + (size_t)(bn + row) * FDIM + k0 + pc * 8);
        }
    };

    float acc[4][8][4];
#pragma unroll
    for (int i = 0; i < 4; i++)
#pragma unroll
        for (int j = 0; j < 8; j++)
#pragma unroll
            for (int q = 0; q < 4; q++) acc[i][j][q] = 0.f;

    const int a_row = warp_m * 64 + (lane & 15);
    const int a_ch  = lane >> 4;
    const int b_row = warp_n * 64 + (lane & 7) + ((lane >> 4) << 3);
    const int b_ch  = (lane >> 3) & 1;

    load_AB1(0, 0); load_B2(0, 0); cp_commit();

    for (int g = 0; g < P2_CHUNKS; g++) {
        cp_wait0();
        __syncthreads();
        const bool more = (g + 1 < P2_CHUNKS);
        if (more) load_AB1((g + 1) & 1, g + 1);

        const int s = g & 1;
        const uint32_t sA  = sb + s * P2_STAGE;
        const uint32_t sB1 = sA + 16384;
        const uint32_t sB2 = sA + 32768;
#pragma unroll
        for (int ks = 0; ks < 4; ks++) {
            uint32_t a[4][4], aw[4][4], b[4][4];
#pragma unroll
            for (int mi = 0; mi < 4; mi++) {
                ldm_x4(sA + swz128(a_row + mi * 16, ks * 2 + a_ch),
                       a[mi][0], a[mi][1], a[mi][2], a[mi][3]);
#pragma unroll
                for (int t = 0; t < 4; t++) aw[mi][t] = h2sq(a[mi][t]);
            }
            // pass 1: Xw x B1
#pragma unroll
            for (int nj = 0; nj < 4; nj++)
                ldm_x4(sB1 + swz128(b_row + nj * 16, ks * 2 + b_ch),
                       b[nj][0], b[nj][1], b[nj][2], b[nj][3]);
#pragma unroll
            for (int mi = 0; mi < 4; mi++)
#pragma unroll
                for (int ni = 0; ni < 8; ni++)
                    mma16816(acc[mi][ni], aw[mi], &b[ni >> 1][(ni & 1) * 2]);
            // de-batched second half of next chunk's loads
            if (ks == 0) {
                if (more) load_B2((g + 1) & 1, g + 1);
                cp_commit();
            }
            // pass 2: Xp x B2
#pragma unroll
            for (int nj = 0; nj < 4; nj++)
                ldm_x4(sB2 + swz128(b_row + nj * 16, ks * 2 + b_ch),
                       b[nj][0], b[nj][1], b[nj][2], b[nj][3]);
#pragma unroll
            for (int mi = 0; mi < 4; mi++)
#pragma unroll
                for (int ni = 0; ni < 8; ni++)
                    mma16816(acc[mi][ni], a[mi], &b[ni >> 1][(ni & 1) * 2]);
        }
    }

    // ---- staged, coalesced epilogue with fused partial-sum finalize ----
    __syncthreads();
    float* cst  = reinterpret_cast<float*>(smem);
    float* xs_s = cst + P2_SUMOFF;          // 128 floats
    float* pw_s = xs_s + BM;                // 128 floats

    const float al = alpha[h], be = beta[h];
    {   // each thread finalizes one row sum and one col sum
        const float* xp = g_xpart + ((size_t)h * BDIM + bm + tid) * 32;
        const float* pp = g_ppart + ((size_t)h * PDIM + bn + tid) * 32;
        float sx = 0.f, sp = 0.f;
#pragma unroll
        for (int j = 0; j < 32; j += 4) {
            const float4 vx = *reinterpret_cast<const float4*>(xp + j);
            const float4 vp = *reinterpret_cast<const float4*>(pp + j);
            sx += (vx.x + vx.y) + (vx.z + vx.w);
            sp += (vp.x + vp.y) + (vp.z + vp.w);
        }
        xs_s[tid] = al * sx;
        pw_s[tid] = be * sp;
    }

    const int st_r = warp_m * 64 + (lane >> 2);
    const int st_c = warp_n * 64 + (lane & 3) * 2;
#pragma unroll
    for (int mi = 0; mi < 4; mi++)
#pragma unroll
        for (int ni = 0; ni < 8; ni++)
#pragma unroll
            for (int q = 0; q < 2; q++) {
                float* p = cst + (st_r + mi * 16 + q * 8) * P2_PITCHW + st_c + ni * 8;
                p[0] = acc[mi][ni][q * 2 + 0];
                p[1] = acc[mi][ni][q * 2 + 1];
            }
    __syncthreads();

#pragma unroll
    for (int i = 0; i < 32; i++) {
        const int idx = tid + i * P2_THREADS;
        const int r = idx >> 5, c = (idx & 31) * 4;
        const float4 v = *reinterpret_cast<const float4*>(cst + r * P2_PITCHW + c);
        const float xs = xs_s[r];
        const float4 pw = *reinterpret_cast<const float4*>(pw_s + c);
        float4 o;
        o.x = v.x - xs - pw.x;
        o.y = v.y - xs - pw.y;
        o.z = v.z - xs - pw.z;
        o.w = v.w - xs - pw.w;
        *reinterpret_cast<float4*>(out + (size_t)(bm + r) * (HEADS * PDIM) + h * PDIM + bn + c) = o;
    }
}

// ---------------- launch ----------------
extern "C" void kernel_launch(void* const* d_in, const int* in_sizes, int n_in,
                              void* d_out, int out_size) {
    (void)in_sizes; (void)n_in; (void)out_size;
    const float* x     = (const float*)d_in[0];
    const float* feat  = (const float*)d_in[1];
    const float* proto = (const float*)d_in[2];
    const float* theta = (const float*)d_in[3];
    const float* alpha = (const float*)d_in[4];
    const float* beta  = (const float*)d_in[5];
    float* out = (float*)d_out;

    cudaFuncSetAttribute(p2_kernel, cudaFuncAttributeMaxDynamicSharedMemorySize, P2_SMEM);

    convert_kernel<<<(FDIM * TOTALD + 255) / 256, 256>>>(x, feat, proto);

    // merged phase-0/1: x-phase (y<16) + p-phase (y>=16) in one wave-packed launch
    p01_kernel<<<dim3(FDIM / BN, HEADS + PDIM / BM, HEADS), NTHREADS, P01_SMEM>>>(theta, alpha, beta);

    p2_kernel<<<dim3(PDIM / BN, BDIM / BM, HEADS), P2_THREADS, P2_SMEM>>>(alpha, beta, out);
}

// round 15
// speedup vs baseline: 1.1549x; 1.1549x over previous
#include <cuda_runtime.h>
#include <cuda_fp16.h>
#include <cstdint>

// ---------------- problem constants ----------------
#define HEADS  16
#define BDIM   2048
#define DHEAD  64
#define TOTALD 1024
#define FDIM   4096
#define PDIM   512

#define BM 128
#define BN 128
#define BK 32
#define NTHREADS 256

// ---------------- static scratch (no allocations allowed) ----------------
__device__ __half g_x16[(size_t)BDIM * TOTALD];
__device__ __half g_f16[(size_t)FDIM * TOTALD];
__device__ __half g_p16[(size_t)PDIM * TOTALD];
__device__ __half g_Xp[(size_t)HEADS * BDIM * FDIM];   // relu(xf); Xw = Xp^2 derived in p2
__device__ __half g_B1[(size_t)HEADS * PDIM * FDIM];   // th*Pw + al*Pp
__device__ __half g_B2[(size_t)HEADS * PDIM * FDIM];   // be*Pw
__device__ float  g_xpart[(size_t)HEADS * BDIM * 32];
__device__ float  g_ppart[(size_t)HEADS * PDIM * 32];

// ---------------- helpers ----------------
__device__ __forceinline__ uint32_t smem_u32(const void* p) {
    return (uint32_t)__cvta_generic_to_shared(p);
}
__device__ __forceinline__ void cp_async16(uint32_t dst, const void* src) {
    asm volatile("cp.async.cg.shared.global [%0], [%1], 16;\n" :: "r"(dst), "l"(src));
}
__device__ __forceinline__ void cp_commit() { asm volatile("cp.async.commit_group;\n"); }
__device__ __forceinline__ void cp_wait1()  { asm volatile("cp.async.wait_group 1;\n"); }
__device__ __forceinline__ void cp_wait0()  { asm volatile("cp.async.wait_group 0;\n"); }

// 64B rows, 4x16B chunks swizzle (p0/p1)
__device__ __forceinline__ uint32_t swoff(int row, int chunk) {
    return (uint32_t)(row * 64 + ((chunk ^ ((row >> 1) & 3)) << 4));
}
// 128B rows, 8x16B chunks swizzle (p2)
__device__ __forceinline__ uint32_t swz128(int row, int c) {
    return (uint32_t)(row * 128 + ((c ^ (row & 7)) << 4));
}
__device__ __forceinline__ void ldm_x4(uint32_t addr, uint32_t& r0, uint32_t& r1,
                                       uint32_t& r2, uint32_t& r3) {
    asm volatile("ldmatrix.sync.aligned.m8n8.x4.shared.b16 {%0,%1,%2,%3}, [%4];\n"
                 : "=r"(r0), "=r"(r1), "=r"(r2), "=r"(r3) : "r"(addr));
}
__device__ __forceinline__ void mma16816(float* c, const uint32_t* a, const uint32_t* b) {
    asm volatile("mma.sync.aligned.m16n8k16.row.col.f32.f16.f16.f32 "
                 "{%0,%1,%2,%3}, {%4,%5,%6,%7}, {%8,%9}, {%0,%1,%2,%3};\n"
                 : "+f"(c[0]), "+f"(c[1]), "+f"(c[2]), "+f"(c[3])
                 : "r"(a[0]), "r"(a[1]), "r"(a[2]), "r"(a[3]), "r"(b[0]), "r"(b[1]));
}
__device__ __forceinline__ uint32_t h2sq(uint32_t v) {
    __half2 h = *reinterpret_cast<__half2*>(&v);
    h = __hmul2(h, h);
    return *reinterpret_cast<uint32_t*>(&h);
}

// ---------------- fp32 -> fp16 converts (vectorized, range-partitioned) ----------------
#define CV_NX (BDIM * TOTALD / 4)       // 524288 float4s
#define CV_NF (FDIM * TOTALD / 4)       // 1048576
#define CV_NP (PDIM * TOTALD / 4)       // 131072
#define CV_TOTAL (CV_NX + CV_NF + CV_NP)

__global__ void convert_kernel(const float* __restrict__ x,
                               const float* __restrict__ f,
                               const float* __restrict__ p) {
    const int i = blockIdx.x * blockDim.x + threadIdx.x;
    if (i >= CV_TOTAL) return;
    const float4* src;
    uint2* dst;
    int j;
    if (i < CV_NX)            { j = i;                src = (const float4*)x + j; dst = (uint2*)g_x16 + j; }
    else if (i < CV_NX+CV_NF) { j = i - CV_NX;        src = (const float4*)f + j; dst = (uint2*)g_f16 + j; }
    else                      { j = i - CV_NX - CV_NF; src = (const float4*)p + j; dst = (uint2*)g_p16 + j; }
    const float4 v = *src;
    const __half2 h0 = __floats2half2_rn(v.x, v.y);
    const __half2 h1 = __floats2half2_rn(v.z, v.w);
    uint2 o;
    o.x = *reinterpret_cast<const uint32_t*>(&h0);
    o.y = *reinterpret_cast<const uint32_t*>(&h1);
    *dst = o;
}

// ---------------- phase-0/1 GEMMs (K=64) with fused row-sums + coalesced stores ----------------
#define P01_PITCH 272
#define P01_SMEM (BM * P01_PITCH)

template <int PHASE>
__global__ void __launch_bounds__(NTHREADS)
gemm_kernel(const float* __restrict__ theta, const float* __restrict__ alpha,
            const float* __restrict__ beta) {
    extern __shared__ __align__(1024) uint8_t smem[];

    const int tid    = threadIdx.x;
    const int lane   = tid & 31;
    const int warp   = tid >> 5;
    const int warp_m = warp & 3;
    const int warp_n = warp >> 2;
    const int h  = blockIdx.z;
    const int bm = blockIdx.y * BM;
    const int bn = blockIdx.x * BN;

    const __half* A = (PHASE == 0 ? g_x16 : g_p16) + h * DHEAD;
    const __half* B = g_f16 + h * DHEAD;
    const int total_kt = DHEAD / BK;
    const uint32_t sbase = smem_u32(smem);

    auto load_tile = [&](int s, int g) {
        const int k0 = g * BK;
        int idx = tid;
#pragma unroll
        for (int r = 0; r < 2; r++, idx += NTHREADS) {
            int row = idx >> 2, ch = idx & 3;
            cp_async16(sbase + s * 8192 + swoff(row, ch),
                       A + (size_t)(bm + row) * TOTALD + k0 + ch * 8);
        }
        idx = tid;
#pragma unroll
        for (int r = 0; r < 2; r++, idx += NTHREADS) {
            int row = idx >> 2, ch = idx & 3;
            cp_async16(sbase + 16384 + s * 8192 + swoff(row, ch),
                       B + (size_t)(bn + row) * TOTALD + k0 + ch * 8);
        }
    };

    float acc[2][8][4];
#pragma unroll
    for (int i = 0; i < 2; i++)
#pragma unroll
        for (int j = 0; j < 8; j++)
#pragma unroll
            for (int q = 0; q < 4; q++) acc[i][j][q] = 0.f;

    const int a_row = warp_m * 32 + (lane & 15);
    const int a_ch  = lane >> 4;
    const int b_row = warp_n * 64 + (lane & 7) + ((lane >> 4) << 3);
    const int b_ch  = (lane >> 3) & 1;

    load_tile(0, 0);
    cp_commit();

    for (int g = 0; g < total_kt; g++) {
        if (g + 1 < total_kt) { load_tile((g + 1) & 1, g + 1); cp_commit(); cp_wait1(); }
        else                  { cp_wait0(); }
        __syncthreads();

        const int s = g & 1;
        const uint32_t sA = sbase + s * 8192;
        const uint32_t sB = sbase + 16384 + s * 8192;
#pragma unroll
        for (int ks = 0; ks < 2; ks++) {
            uint32_t a[2][4];
#pragma unroll
            for (int mi = 0; mi < 2; mi++)
                ldm_x4(sA + swoff(a_row + mi * 16, ks * 2 + a_ch),
                       a[mi][0], a[mi][1], a[mi][2], a[mi][3]);
            uint32_t b[4][4];
#pragma unroll
            for (int nj = 0; nj < 4; nj++)
                ldm_x4(sB + swoff(b_row + nj * 16, ks * 2 + b_ch),
                       b[nj][0], b[nj][1], b[nj][2], b[nj][3]);
#pragma unroll
            for (int mi = 0; mi < 2; mi++)
#pragma unroll
                for (int ni = 0; ni < 8; ni++)
                    mma16816(acc[mi][ni], a[mi], &b[ni >> 1][(ni & 1) * 2]);
        }
        __syncthreads();
    }

    // ---- row-sum partials (w = relu(acc)^2) ----
    float th = 0.f, al = 0.f, be = 0.f;
    if (PHASE == 1) { th = theta[h]; al = alpha[h]; be = beta[h]; }

    float rowsum[2][2] = {{0.f, 0.f}, {0.f, 0.f}};
#pragma unroll
    for (int mi = 0; mi < 2; mi++)
#pragma unroll
        for (int ni = 0; ni < 8; ni++)
#pragma unroll
            for (int q = 0; q < 2; q++) {
                const float p0 = fmaxf(acc[mi][ni][q * 2 + 0], 0.f);
                const float p1 = fmaxf(acc[mi][ni][q * 2 + 1], 0.f);
                rowsum[mi][q] += p0 * p0 + p1 * p1;
            }
#pragma unroll
    for (int mi = 0; mi < 2; mi++)
#pragma unroll
        for (int q = 0; q < 2; q++) {
            float s = rowsum[mi][q];
            s += __shfl_xor_sync(0xffffffffu, s, 1);
            s += __shfl_xor_sync(0xffffffffu, s, 2);
            rowsum[mi][q] = s;
        }
    float* red = reinterpret_cast<float*>(smem);
    if (warp_n == 0 && (lane & 3) == 0) {
#pragma unroll
        for (int mi = 0; mi < 2; mi++)
#pragma unroll
            for (int q = 0; q < 2; q++)
                red[warp_m * 32 + mi * 16 + q * 8 + (lane >> 2)] = rowsum[mi][q];
    }
    __syncthreads();
    if (warp_n == 1 && (lane & 3) == 0) {
#pragma unroll
        for (int mi = 0; mi < 2; mi++)
#pragma unroll
            for (int q = 0; q < 2; q++) {
                const int rl = warp_m * 32 + mi * 16 + q * 8 + (lane >> 2);
                const float tot = red[rl] + rowsum[mi][q];
                if (PHASE == 0)
                    g_xpart[((size_t)h * BDIM + bm + rl) * 32 + blockIdx.x] = tot;
                else
                    g_ppart[((size_t)h * PDIM + bm + rl) * 32 + blockIdx.x] = tot;
            }
    }

    // ---- staged, coalesced output passes (1 pass for PHASE 0, 2 for PHASE 1) ----
    const int st_r = warp_m * 32 + (lane >> 2);
    const int st_c = warp_n * 64 + (lane & 3) * 2;
    const int npass = (PHASE == 0) ? 1 : 2;
#pragma unroll
    for (int pass = 0; pass < npass; pass++) {
        __syncthreads();
#pragma unroll
        for (int mi = 0; mi < 2; mi++)
#pragma unroll
            for (int ni = 0; ni < 8; ni++)
#pragma unroll
                for (int q = 0; q < 2; q++) {
                    const float p0 = fmaxf(acc[mi][ni][q * 2 + 0], 0.f);
                    const float p1 = fmaxf(acc[mi][ni][q * 2 + 1], 0.f);
                    const float w0 = p0 * p0, w1 = p1 * p1;
                    __half2 v;
                    if (PHASE == 0)
                        v = __floats2half2_rn(p0, p1);
                    else
                        v = (pass == 0) ? __floats2half2_rn(th * w0 + al * p0,
                                                            th * w1 + al * p1)
                                        : __floats2half2_rn(be * w0, be * w1);
                    *reinterpret_cast<__half2*>(smem +
                        (st_r + mi * 16 + q * 8) * P01_PITCH + (st_c + ni * 8) * 2) = v;
                }
        __syncthreads();
        __half* dst;
        if (PHASE == 0) dst = g_Xp + (size_t)h * BDIM * FDIM;
        else            dst = (pass == 0 ? g_B1 : g_B2) + (size_t)h * PDIM * FDIM;
#pragma unroll
        for (int i = 0; i < 8; i++) {
            const int idx = tid + i * NTHREADS;
            const int r = idx >> 4, c = idx & 15;
            const uint4 v = *reinterpret_cast<const uint4*>(smem + r * P01_PITCH + c * 16);
            *reinterpret_cast<uint4*>(dst + (size_t)(bm + r) * FDIM + bn + c * 8) = v;
        }
    }
}

// ---------------- phase-2: R8 mainloop (BK=64, 2-stage, interleaved passes) ----------------
#define P2_THREADS 128
#define P2_BK 64
#define P2_CHUNKS 64
#define P2_STAGE (3 * BM * P2_BK * 2)         // Xp 16KB + B1 16KB + B2 16KB = 48KB
#define P2_SMEM (2 * P2_STAGE)                // 96KB -> 2 CTAs/SM
#define P2_PITCHW 136
#define P2_SUMOFF (BM * P2_PITCHW)

__global__ void __launch_bounds__(P2_THREADS, 2)
p2_kernel(const float* __restrict__ alpha, const float* __restrict__ beta,
          float* __restrict__ out) {
    extern __shared__ __align__(1024) uint8_t smem[];
    const uint32_t sb = smem_u32(smem);
    const int tid    = threadIdx.x;
    const int lane   = tid & 31;
    const int warp   = tid >> 5;
    const int warp_m = warp & 1;
    const int warp_n = warp >> 1;
    const int h  = blockIdx.z;
    const int bm = blockIdx.y * BM;
    const int bn = blockIdx.x * BN;

    const __half* Ap = g_Xp + (size_t)h * BDIM * FDIM;
    const __half* B1 = g_B1 + (size_t)h * PDIM * FDIM;
    const __half* B2 = g_B2 + (size_t)h * PDIM * FDIM;

    auto load_tile = [&](int s, int g) {
        const int k0 = g * P2_BK;
        const uint32_t sA  = sb + s * P2_STAGE;
        const uint32_t sB1 = sA + 16384;
        const uint32_t sB2 = sA + 32768;
        const int pr = tid >> 3, pc = tid & 7;
#pragma unroll
        for (int i = 0; i < 8; i++) {
            const int row = i * 16 + pr;
            cp_async16(sA + swz128(row, pc), Ap + (size_t)(bm + row) * FDIM + k0 + pc * 8);
        }
#pragma unroll
        for (int i = 0; i < 8; i++) {
            const int row = i * 16 + pr;
            cp_async16(sB1 + swz128(row, pc), B1 + (size_t)(bn + row) * FDIM + k0 + pc * 8);
        }
#pragma unroll
        for (int i = 0; i < 8; i++) {
            const int row = i * 16 + pr;
            cp_async16(sB2 + swz128(row, pc), B2 + (size_t)(bn + row) * FDIM + k0 + pc * 8);
        }
    };

    float acc[4][8][4];
#pragma unroll
    for (int i = 0; i < 4; i++)
#pragma unroll
        for (int j = 0; j < 8; j++)
#pragma unroll
            for (int q = 0; q < 4; q++) acc[i][j][q] = 0.f;

    const int a_row = warp_m * 64 + (lane & 15);
    const int a_ch  = lane >> 4;
    const int b_row = warp_n * 64 + (lane & 7) + ((lane >> 4) << 3);
    const int b_ch  = (lane >> 3) & 1;

    load_tile(0, 0); cp_commit();

    for (int g = 0; g < P2_CHUNKS; g++) {
        cp_wait0();
        __syncthreads();
        if (g + 1 < P2_CHUNKS) { load_tile((g + 1) & 1, g + 1); cp_commit(); }

        const int s = g & 1;
        const uint32_t sA  = sb + s * P2_STAGE;
        const uint32_t sB1 = sA + 16384;
        const uint32_t sB2 = sA + 32768;
#pragma unroll
        for (int ks = 0; ks < 4; ks++) {
            uint32_t a[4][4], aw[4][4], b[4][4];
#pragma unroll
            for (int mi = 0; mi < 4; mi++) {
                ldm_x4(sA + swz128(a_row + mi * 16, ks * 2 + a_ch),
                       a[mi][0], a[mi][1], a[mi][2], a[mi][3]);
#pragma unroll
                for (int t = 0; t < 4; t++) aw[mi][t] = h2sq(a[mi][t]);
            }
            // pass 1: Xw x B1
#pragma unroll
            for (int nj = 0; nj < 4; nj++)
                ldm_x4(sB1 + swz128(b_row + nj * 16, ks * 2 + b_ch),
                       b[nj][0], b[nj][1], b[nj][2], b[nj][3]);
#pragma unroll
            for (int mi = 0; mi < 4; mi++)
#pragma unroll
                for (int ni = 0; ni < 8; ni++)
                    mma16816(acc[mi][ni], aw[mi], &b[ni >> 1][(ni & 1) * 2]);
            // pass 2: Xp x B2
#pragma unroll
            for (int nj = 0; nj < 4; nj++)
                ldm_x4(sB2 + swz128(b_row + nj * 16, ks * 2 + b_ch),
                       b[nj][0], b[nj][1], b[nj][2], b[nj][3]);
#pragma unroll
            for (int mi = 0; mi < 4; mi++)
#pragma unroll
                for (int ni = 0; ni < 8; ni++)
                    mma16816(acc[mi][ni], a[mi], &b[ni >> 1][(ni & 1) * 2]);
        }
    }

    // ---- staged, coalesced epilogue with fused partial-sum finalize ----
    __syncthreads();
    float* cst  = reinterpret_cast<float*>(smem);
    float* xs_s = cst + P2_SUMOFF;          // 128 floats
    float* pw_s = xs_s + BM;                // 128 floats

    const float al = alpha[h], be = beta[h];
    {   // each thread finalizes one row sum and one col sum
        const float* xp = g_xpart + ((size_t)h * BDIM + bm + tid) * 32;
        const float* pp = g_ppart + ((size_t)h * PDIM + bn + tid) * 32;
        float sx = 0.f, sp = 0.f;
#pragma unroll
        for (int j = 0; j < 32; j += 4) {
            const float4 vx = *reinterpret_cast<const float4*>(xp + j);
            const float4 vp = *reinterpret_cast<const float4*>(pp + j);
            sx += (vx.x + vx.y) + (vx.z + vx.w);
            sp += (vp.x + vp.y) + (vp.z + vp.w);
        }
        xs_s[tid] = al * sx;
        pw_s[tid] = be * sp;
    }

    const int st_r = warp_m * 64 + (lane >> 2);
    const int st_c = warp_n * 64 + (lane & 3) * 2;
#pragma unroll
    for (int mi = 0; mi < 4; mi++)
#pragma unroll
        for (int ni = 0; ni < 8; ni++)
#pragma unroll
            for (int q = 0; q < 2; q++) {
                float* p = cst + (st_r + mi * 16 + q * 8) * P2_PITCHW + st_c + ni * 8;
                p[0] = acc[mi][ni][q * 2 + 0];
                p[1] = acc[mi][ni][q * 2 + 1];
            }
    __syncthreads();

#pragma unroll
    for (int i = 0; i < 32; i++) {
        const int idx = tid + i * P2_THREADS;
        const int r = idx >> 5, c = (idx & 31) * 4;
        const float4 v = *reinterpret_cast<const float4*>(cst + r * P2_PITCHW + c);
        const float xs = xs_s[r];
        const float4 pw = *reinterpret_cast<const float4*>(pw_s + c);
        float4 o;
        o.x = v.x - xs - pw.x;
        o.y = v.y - xs - pw.y;
        o.z = v.z - xs - pw.z;
        o.w = v.w - xs - pw.w;
        *reinterpret_cast<float4*>(out + (size_t)(bm + r) * (HEADS * PDIM) + h * PDIM + bn + c) = o;
    }
}

// ---------------- launch ----------------
extern "C" void kernel_launch(void* const* d_in, const int* in_sizes, int n_in,
                              void* d_out, int out_size) {
    (void)in_sizes; (void)n_in; (void)out_size;
    const float* x     = (const float*)d_in[0];
    const float* feat  = (const float*)d_in[1];
    const float* proto = (const float*)d_in[2];
    const float* theta = (const float*)d_in[3];
    const float* alpha = (const float*)d_in[4];
    const float* beta  = (const float*)d_in[5];
    float* out = (float*)d_out;

    cudaFuncSetAttribute(p2_kernel, cudaFuncAttributeMaxDynamicSharedMemorySize, P2_SMEM);

    convert_kernel<<<(CV_TOTAL + 255) / 256, 256>>>(x, feat, proto);

    gemm_kernel<0><<<dim3(FDIM / BN, BDIM / BM, HEADS), NTHREADS, P01_SMEM>>>(theta, alpha, beta);
    gemm_kernel<1><<<dim3(FDIM / BN, PDIM / BM, HEADS), NTHREADS, P01_SMEM>>>(theta, alpha, beta);

    p2_kernel<<<dim3(PDIM / BN, BDIM / BM, HEADS), P2_THREADS, P2_SMEM>>>(alpha, beta, out);
}

// round 16
// speedup vs baseline: 1.1643x; 1.0081x over previous
#include <cuda_runtime.h>
#include <cuda_fp16.h>
#include <cstdint>

// ---------------- problem constants ----------------
#define HEADS  16
#define BDIM   2048
#define DHEAD  64
#define TOTALD 1024
#define FDIM   4096
#define PDIM   512

#define BM 128
#define BN 128
#define BK 32
#define NTHREADS 256

// ---------------- static scratch (no allocations allowed) ----------------
__device__ __half g_x16[(size_t)BDIM * TOTALD];
__device__ __half g_f16[(size_t)FDIM * TOTALD];
__device__ __half g_p16[(size_t)PDIM * TOTALD];
__device__ __half g_Xp[(size_t)HEADS * BDIM * FDIM];   // relu(xf); Xw = Xp^2 derived in p2
__device__ __half g_B1[(size_t)HEADS * PDIM * FDIM];   // th*Pw + al*Pp
__device__ __half g_B2[(size_t)HEADS * PDIM * FDIM];   // be*Pw
__device__ float  g_xpart[(size_t)HEADS * BDIM * 32];
__device__ float  g_ppart[(size_t)HEADS * PDIM * 32];

// ---------------- helpers ----------------
__device__ __forceinline__ uint32_t smem_u32(const void* p) {
    return (uint32_t)__cvta_generic_to_shared(p);
}
__device__ __forceinline__ void cp_async16(uint32_t dst, const void* src) {
    asm volatile("cp.async.cg.shared.global [%0], [%1], 16;\n" :: "r"(dst), "l"(src));
}
__device__ __forceinline__ void cp_commit() { asm volatile("cp.async.commit_group;\n"); }
__device__ __forceinline__ void cp_wait1()  { asm volatile("cp.async.wait_group 1;\n"); }
__device__ __forceinline__ void cp_wait0()  { asm volatile("cp.async.wait_group 0;\n"); }

// 64B rows, 4x16B chunks swizzle (p0/p1)
__device__ __forceinline__ uint32_t swoff(int row, int chunk) {
    return (uint32_t)(row * 64 + ((chunk ^ ((row >> 1) & 3)) << 4));
}
// 128B rows, 8x16B chunks swizzle (p2)
__device__ __forceinline__ uint32_t swz128(int row, int c) {
    return (uint32_t)(row * 128 + ((c ^ (row & 7)) << 4));
}
__device__ __forceinline__ void ldm_x4(uint32_t addr, uint32_t& r0, uint32_t& r1,
                                       uint32_t& r2, uint32_t& r3) {
    asm volatile("ldmatrix.sync.aligned.m8n8.x4.shared.b16 {%0,%1,%2,%3}, [%4];\n"
                 : "=r"(r0), "=r"(r1), "=r"(r2), "=r"(r3) : "r"(addr));
}
__device__ __forceinline__ void mma16816(float* c, const uint32_t* a, const uint32_t* b) {
    asm volatile("mma.sync.aligned.m16n8k16.row.col.f32.f16.f16.f32 "
                 "{%0,%1,%2,%3}, {%4,%5,%6,%7}, {%8,%9}, {%0,%1,%2,%3};\n"
                 : "+f"(c[0]), "+f"(c[1]), "+f"(c[2]), "+f"(c[3])
                 : "r"(a[0]), "r"(a[1]), "r"(a[2]), "r"(a[3]), "r"(b[0]), "r"(b[1]));
}
__device__ __forceinline__ uint32_t h2sq(uint32_t v) {
    __half2 h = *reinterpret_cast<__half2*>(&v);
    h = __hmul2(h, h);
    return *reinterpret_cast<uint32_t*>(&h);
}

// ---------------- fp32 -> fp16 converts (vectorized, range-partitioned) ----------------
#define CV_NX (BDIM * TOTALD / 4)
#define CV_NF (FDIM * TOTALD / 4)
#define CV_NP (PDIM * TOTALD / 4)
#define CV_TOTAL (CV_NX + CV_NF + CV_NP)

__global__ void convert_kernel(const float* __restrict__ x,
                               const float* __restrict__ f,
                               const float* __restrict__ p) {
    const int i = blockIdx.x * blockDim.x + threadIdx.x;
    if (i >= CV_TOTAL) return;
    const float4* src;
    uint2* dst;
    int j;
    if (i < CV_NX)            { j = i;                 src = (const float4*)x + j; dst = (uint2*)g_x16 + j; }
    else if (i < CV_NX+CV_NF) { j = i - CV_NX;         src = (const float4*)f + j; dst = (uint2*)g_f16 + j; }
    else                      { j = i - CV_NX - CV_NF; src = (const float4*)p + j; dst = (uint2*)g_p16 + j; }
    const float4 v = *src;
    const __half2 h0 = __floats2half2_rn(v.x, v.y);
    const __half2 h1 = __floats2half2_rn(v.z, v.w);
    uint2 o;
    o.x = *reinterpret_cast<const uint32_t*>(&h0);
    o.y = *reinterpret_cast<const uint32_t*>(&h1);
    *dst = o;
}

// ---------------- phase-0/1 GEMMs (K=64) with fused row-sums + coalesced stores ----------------
#define P01_PITCH 272
#define P01_SMEM (BM * P01_PITCH)

template <int PHASE>
__global__ void __launch_bounds__(NTHREADS)
gemm_kernel(const float* __restrict__ theta, const float* __restrict__ alpha,
            const float* __restrict__ beta) {
    extern __shared__ __align__(1024) uint8_t smem[];

    const int tid    = threadIdx.x;
    const int lane   = tid & 31;
    const int warp   = tid >> 5;
    const int warp_m = warp & 3;
    const int warp_n = warp >> 2;
    const int h  = blockIdx.z;
    const int bm = blockIdx.y * BM;
    const int bn = blockIdx.x * BN;

    const __half* A = (PHASE == 0 ? g_x16 : g_p16) + h * DHEAD;
    const __half* B = g_f16 + h * DHEAD;
    const int total_kt = DHEAD / BK;
    const uint32_t sbase = smem_u32(smem);

    auto load_tile = [&](int s, int g) {
        const int k0 = g * BK;
        int idx = tid;
#pragma unroll
        for (int r = 0; r < 2; r++, idx += NTHREADS) {
            int row = idx >> 2, ch = idx & 3;
            cp_async16(sbase + s * 8192 + swoff(row, ch),
                       A + (size_t)(bm + row) * TOTALD + k0 + ch * 8);
        }
        idx = tid;
#pragma unroll
        for (int r = 0; r < 2; r++, idx += NTHREADS) {
            int row = idx >> 2, ch = idx & 3;
            cp_async16(sbase + 16384 + s * 8192 + swoff(row, ch),
                       B + (size_t)(bn + row) * TOTALD + k0 + ch * 8);
        }
    };

    float acc[2][8][4];
#pragma unroll
    for (int i = 0; i < 2; i++)
#pragma unroll
        for (int j = 0; j < 8; j++)
#pragma unroll
            for (int q = 0; q < 4; q++) acc[i][j][q] = 0.f;

    const int a_row = warp_m * 32 + (lane & 15);
    const int a_ch  = lane >> 4;
    const int b_row = warp_n * 64 + (lane & 7) + ((lane >> 4) << 3);
    const int b_ch  = (lane >> 3) & 1;

    load_tile(0, 0);
    cp_commit();

    for (int g = 0; g < total_kt; g++) {
        if (g + 1 < total_kt) { load_tile((g + 1) & 1, g + 1); cp_commit(); cp_wait1(); }
        else                  { cp_wait0(); }
        __syncthreads();

        const int s = g & 1;
        const uint32_t sA = sbase + s * 8192;
        const uint32_t sB = sbase + 16384 + s * 8192;
#pragma unroll
        for (int ks = 0; ks < 2; ks++) {
            uint32_t a[2][4];
#pragma unroll
            for (int mi = 0; mi < 2; mi++)
                ldm_x4(sA + swoff(a_row + mi * 16, ks * 2 + a_ch),
                       a[mi][0], a[mi][1], a[mi][2], a[mi][3]);
            uint32_t b[4][4];
#pragma unroll
            for (int nj = 0; nj < 4; nj++)
                ldm_x4(sB + swoff(b_row + nj * 16, ks * 2 + b_ch),
                       b[nj][0], b[nj][1], b[nj][2], b[nj][3]);
#pragma unroll
            for (int mi = 0; mi < 2; mi++)
#pragma unroll
                for (int ni = 0; ni < 8; ni++)
                    mma16816(acc[mi][ni], a[mi], &b[ni >> 1][(ni & 1) * 2]);
        }
        __syncthreads();
    }

    // ---- row-sum partials (w = relu(acc)^2) ----
    float th = 0.f, al = 0.f, be = 0.f;
    if (PHASE == 1) { th = theta[h]; al = alpha[h]; be = beta[h]; }

    float rowsum[2][2] = {{0.f, 0.f}, {0.f, 0.f}};
#pragma unroll
    for (int mi = 0; mi < 2; mi++)
#pragma unroll
        for (int ni = 0; ni < 8; ni++)
#pragma unroll
            for (int q = 0; q < 2; q++) {
                const float p0 = fmaxf(acc[mi][ni][q * 2 + 0], 0.f);
                const float p1 = fmaxf(acc[mi][ni][q * 2 + 1], 0.f);
                rowsum[mi][q] += p0 * p0 + p1 * p1;
            }
#pragma unroll
    for (int mi = 0; mi < 2; mi++)
#pragma unroll
        for (int q = 0; q < 2; q++) {
            float s = rowsum[mi][q];
            s += __shfl_xor_sync(0xffffffffu, s, 1);
            s += __shfl_xor_sync(0xffffffffu, s, 2);
            rowsum[mi][q] = s;
        }
    float* red = reinterpret_cast<float*>(smem);
    if (warp_n == 0 && (lane & 3) == 0) {
#pragma unroll
        for (int mi = 0; mi < 2; mi++)
#pragma unroll
            for (int q = 0; q < 2; q++)
                red[warp_m * 32 + mi * 16 + q * 8 + (lane >> 2)] = rowsum[mi][q];
    }
    __syncthreads();
    if (warp_n == 1 && (lane & 3) == 0) {
#pragma unroll
        for (int mi = 0; mi < 2; mi++)
#pragma unroll
            for (int q = 0; q < 2; q++) {
                const int rl = warp_m * 32 + mi * 16 + q * 8 + (lane >> 2);
                const float tot = red[rl] + rowsum[mi][q];
                if (PHASE == 0)
                    g_xpart[((size_t)h * BDIM + bm + rl) * 32 + blockIdx.x] = tot;
                else
                    g_ppart[((size_t)h * PDIM + bm + rl) * 32 + blockIdx.x] = tot;
            }
    }

    // ---- staged, coalesced output passes (1 pass for PHASE 0, 2 for PHASE 1) ----
    const int st_r = warp_m * 32 + (lane >> 2);
    const int st_c = warp_n * 64 + (lane & 3) * 2;
    const int npass = (PHASE == 0) ? 1 : 2;
#pragma unroll
    for (int pass = 0; pass < npass; pass++) {
        __syncthreads();
#pragma unroll
        for (int mi = 0; mi < 2; mi++)
#pragma unroll
            for (int ni = 0; ni < 8; ni++)
#pragma unroll
                for (int q = 0; q < 2; q++) {
                    const float p0 = fmaxf(acc[mi][ni][q * 2 + 0], 0.f);
                    const float p1 = fmaxf(acc[mi][ni][q * 2 + 1], 0.f);
                    const float w0 = p0 * p0, w1 = p1 * p1;
                    __half2 v;
                    if (PHASE == 0)
                        v = __floats2half2_rn(p0, p1);
                    else
                        v = (pass == 0) ? __floats2half2_rn(th * w0 + al * p0,
                                                            th * w1 + al * p1)
                                        : __floats2half2_rn(be * w0, be * w1);
                    *reinterpret_cast<__half2*>(smem +
                        (st_r + mi * 16 + q * 8) * P01_PITCH + (st_c + ni * 8) * 2) = v;
                }
        __syncthreads();
        __half* dst;
        if (PHASE == 0) dst = g_Xp + (size_t)h * BDIM * FDIM;
        else            dst = (pass == 0 ? g_B1 : g_B2) + (size_t)h * PDIM * FDIM;
#pragma unroll
        for (int i = 0; i < 8; i++) {
            const int idx = tid + i * NTHREADS;
            const int r = idx >> 4, c = idx & 15;
            const uint4 v = *reinterpret_cast<const uint4*>(smem + r * P01_PITCH + c * 16);
            *reinterpret_cast<uint4*>(dst + (size_t)(bm + r) * FDIM + bn + c * 8) = v;
        }
    }
}

// ---------------- phase-2: R8 mainloop; bm on fast grid axis; prologue sum finalize ----------------
#define P2_THREADS 128
#define P2_BK 64
#define P2_CHUNKS 64
#define P2_STAGE (3 * BM * P2_BK * 2)         // Xp 16KB + B1 16KB + B2 16KB = 48KB
#define P2_SUMBASE (2 * P2_STAGE)             // 96KB: sums above both stages
#define P2_SMEM (P2_SUMBASE + 1024)           // 97.25KB -> still 2 CTAs/SM (<=114KB)
#define P2_PITCHW 136

__global__ void __launch_bounds__(P2_THREADS, 2)
p2_kernel(const float* __restrict__ alpha, const float* __restrict__ beta,
          float* __restrict__ out) {
    extern __shared__ __align__(1024) uint8_t smem[];
    const uint32_t sb = smem_u32(smem);
    const int tid    = threadIdx.x;
    const int lane   = tid & 31;
    const int warp   = tid >> 5;
    const int warp_m = warp & 1;
    const int warp_n = warp >> 1;
    const int h  = blockIdx.z;
    const int bm = blockIdx.x * BM;   // fast axis: consecutive CTAs share B tiles
    const int bn = blockIdx.y * BN;

    const __half* Ap = g_Xp + (size_t)h * BDIM * FDIM;
    const __half* B1 = g_B1 + (size_t)h * PDIM * FDIM;
    const __half* B2 = g_B2 + (size_t)h * PDIM * FDIM;

    auto load_tile = [&](int s, int g) {
        const int k0 = g * P2_BK;
        const uint32_t sA  = sb + s * P2_STAGE;
        const uint32_t sB1 = sA + 16384;
        const uint32_t sB2 = sA + 32768;
        const int pr = tid >> 3, pc = tid & 7;
#pragma unroll
        for (int i = 0; i < 8; i++) {
            const int row = i * 16 + pr;
            cp_async16(sA + swz128(row, pc), Ap + (size_t)(bm + row) * FDIM + k0 + pc * 8);
        }
#pragma unroll
        for (int i = 0; i < 8; i++) {
            const int row = i * 16 + pr;
            cp_async16(sB1 + swz128(row, pc), B1 + (size_t)(bn + row) * FDIM + k0 + pc * 8);
        }
#pragma unroll
        for (int i = 0; i < 8; i++) {
            const int row = i * 16 + pr;
            cp_async16(sB2 + swz128(row, pc), B2 + (size_t)(bn + row) * FDIM + k0 + pc * 8);
        }
    };

    float acc[4][8][4];
#pragma unroll
    for (int i = 0; i < 4; i++)
#pragma unroll
        for (int j = 0; j < 8; j++)
#pragma unroll
            for (int q = 0; q < 4; q++) acc[i][j][q] = 0.f;

    const int a_row = warp_m * 64 + (lane & 15);
    const int a_ch  = lane >> 4;
    const int b_row = warp_n * 64 + (lane & 7) + ((lane >> 4) << 3);
    const int b_ch  = (lane >> 3) & 1;

    load_tile(0, 0); cp_commit();

    // ---- prologue: finalize row/col sums (gmem latency hidden under first tile load) ----
    float* xs_s = reinterpret_cast<float*>(smem + P2_SUMBASE);        // 128 floats
    float* pw_s = reinterpret_cast<float*>(smem + P2_SUMBASE + 512);  // 128 floats
    {
        const float al = alpha[h], be = beta[h];
        const float* xp = g_xpart + ((size_t)h * BDIM + bm + tid) * 32;
        const float* pp = g_ppart + ((size_t)h * PDIM + bn + tid) * 32;
        float sx = 0.f, sp = 0.f;
#pragma unroll
        for (int j = 0; j < 32; j += 4) {
            const float4 vx = *reinterpret_cast<const float4*>(xp + j);
            const float4 vp = *reinterpret_cast<const float4*>(pp + j);
            sx += (vx.x + vx.y) + (vx.z + vx.w);
            sp += (vp.x + vp.y) + (vp.z + vp.w);
        }
        xs_s[tid] = al * sx;
        pw_s[tid] = be * sp;
    }

    for (int g = 0; g < P2_CHUNKS; g++) {
        cp_wait0();
        __syncthreads();
        if (g + 1 < P2_CHUNKS) { load_tile((g + 1) & 1, g + 1); cp_commit(); }

        const int s = g & 1;
        const uint32_t sA  = sb + s * P2_STAGE;
        const uint32_t sB1 = sA + 16384;
        const uint32_t sB2 = sA + 32768;
#pragma unroll
        for (int ks = 0; ks < 4; ks++) {
            uint32_t a[4][4], aw[4][4], b[4][4];
#pragma unroll
            for (int mi = 0; mi < 4; mi++) {
                ldm_x4(sA + swz128(a_row + mi * 16, ks * 2 + a_ch),
                       a[mi][0], a[mi][1], a[mi][2], a[mi][3]);
#pragma unroll
                for (int t = 0; t < 4; t++) aw[mi][t] = h2sq(a[mi][t]);
            }
            // pass 1: Xw x B1
#pragma unroll
            for (int nj = 0; nj < 4; nj++)
                ldm_x4(sB1 + swz128(b_row + nj * 16, ks * 2 + b_ch),
                       b[nj][0], b[nj][1], b[nj][2], b[nj][3]);
#pragma unroll
            for (int mi = 0; mi < 4; mi++)
#pragma unroll
                for (int ni = 0; ni < 8; ni++)
                    mma16816(acc[mi][ni], aw[mi], &b[ni >> 1][(ni & 1) * 2]);
            // pass 2: Xp x B2
#pragma unroll
            for (int nj = 0; nj < 4; nj++)
                ldm_x4(sB2 + swz128(b_row + nj * 16, ks * 2 + b_ch),
                       b[nj][0], b[nj][1], b[nj][2], b[nj][3]);
#pragma unroll
            for (int mi = 0; mi < 4; mi++)
#pragma unroll
                for (int ni = 0; ni < 8; ni++)
                    mma16816(acc[mi][ni], a[mi], &b[ni >> 1][(ni & 1) * 2]);
        }
    }

    // ---- staged, coalesced epilogue (sums already in smem) ----
    __syncthreads();
    float* cst = reinterpret_cast<float*>(smem);
    const int st_r = warp_m * 64 + (lane >> 2);
    const int st_c = warp_n * 64 + (lane & 3) * 2;
#pragma unroll
    for (int mi = 0; mi < 4; mi++)
#pragma unroll
        for (int ni = 0; ni < 8; ni++)
#pragma unroll
            for (int q = 0; q < 2; q++) {
                float* p = cst + (st_r + mi * 16 + q * 8) * P2_PITCHW + st_c + ni * 8;
                p[0] = acc[mi][ni][q * 2 + 0];
                p[1] = acc[mi][ni][q * 2 + 1];
            }
    __syncthreads();

#pragma unroll
    for (int i = 0; i < 32; i++) {
        const int idx = tid + i * P2_THREADS;
        const int r = idx >> 5, c = (idx & 31) * 4;
        const float4 v = *reinterpret_cast<const float4*>(cst + r * P2_PITCHW + c);
        const float xs = xs_s[r];
        const float4 pw = *reinterpret_cast<const float4*>(pw_s + c);
        float4 o;
        o.x = v.x - xs - pw.x;
        o.y = v.y - xs - pw.y;
        o.z = v.z - xs - pw.z;
        o.w = v.w - xs - pw.w;
        *reinterpret_cast<float4*>(out + (size_t)(bm + r) * (HEADS * PDIM) + h * PDIM + bn + c) = o;
    }
}

// ---------------- launch ----------------
extern "C" void kernel_launch(void* const* d_in, const int* in_sizes, int n_in,
                              void* d_out, int out_size) {
    (void)in_sizes; (void)n_in; (void)out_size;
    const float* x     = (const float*)d_in[0];
    const float* feat  = (const float*)d_in[1];
    const float* proto = (const float*)d_in[2];
    const float* theta = (const float*)d_in[3];
    const float* alpha = (const float*)d_in[4];
    const float* beta  = (const float*)d_in[5];
    float* out = (float*)d_out;

    cudaFuncSetAttribute(p2_kernel, cudaFuncAttributeMaxDynamicSharedMemorySize, P2_SMEM);

    convert_kernel<<<(CV_TOTAL + 255) / 256, 256>>>(x, feat, proto);

    gemm_kernel<0><<<dim3(FDIM / BN, BDIM / BM, HEADS), NTHREADS, P01_SMEM>>>(theta, alpha, beta);
    gemm_kernel<1><<<dim3(FDIM / BN, PDIM / BM, HEADS), NTHREADS, P01_SMEM>>>(theta, alpha, beta);

    // p2: bm on fast axis (B-tile reuse among consecutive CTAs)
    p2_kernel<<<dim3(BDIM / BM, PDIM / BN, HEADS), P2_THREADS, P2_SMEM>>>(alpha, beta, out);
}